// round 2
// baseline (speedup 1.0000x reference)
#include <cuda_runtime.h>
#include <math.h>

// ---------------------------------------------------------------------------
// SeqGraphRepNetwork on GB300 — node-space implementation.
// Key simplifications vs reference:
//  * GAT edge logits: (y @ W^T) @ a == y . (a @ W)  -> precompute 2 vectors.
//  * Chain graph: each node has <=2 incoming edges -> closed-form 2-way softmax.
//  * No padding: all transformer math runs on the N valid nodes only.
// ---------------------------------------------------------------------------

#define NMAX   116000
#define BSESS  1024
#define MAXLEN 160

// Scratch (reused across phases; see kernel_launch for the lifetime plan)
__device__ float g_bufA[NMAX * 128];   // x        -> ctx
__device__ float g_bufB[NMAX * 128];   // H        -> out_proj result
__device__ float g_bufC[NMAX * 128];   // Q (LN1)  -> ffn hidden
__device__ float g_bufD[NMAX * 128];   // q proj   -> ffn out
__device__ float g_bufE[NMAX * 128];   // k proj
__device__ float g_bufF[NMAX * 128];   // v proj
__device__ float g_bufG[NMAX * 128];   // out2 (post-LN2)
__device__ float g_wf[128];
__device__ float g_wb[128];
__device__ int   g_starts[BSESS + 1];

// ---------------- prep: w_f = a_src @ att_W, w_b = a_dst @ att_W ------------
__global__ void k_prep_w(const float* __restrict__ attW,
                         const float* __restrict__ a_src,
                         const float* __restrict__ a_dst) {
    int k = threadIdx.x;  // 0..127
    float f = 0.f, b = 0.f;
    for (int d = 0; d < 128; d++) {
        float w = attW[d * 128 + k];
        f += a_src[d] * w;
        b += a_dst[d] * w;
    }
    g_wf[k] = f;
    g_wb[k] = b;
}

// ---------------- prep: session start offsets (inclusive scan) --------------
__global__ void k_starts(const int* __restrict__ lengths) {
    __shared__ int sm[BSESS];
    int t = threadIdx.x;
    sm[t] = lengths[t];
    __syncthreads();
    for (int off = 1; off < BSESS; off <<= 1) {
        int v = (t >= off) ? sm[t - off] : 0;
        __syncthreads();
        sm[t] += v;
        __syncthreads();
    }
    g_starts[t + 1] = sm[t];
    if (t == 0) g_starts[0] = 0;
}

// ---------------- gather x = POI_embs[sess_idx] -----------------------------
__global__ void k_gather(const float* __restrict__ POI,
                         const int* __restrict__ idx,
                         float* __restrict__ x, int N) {
    int t = blockIdx.x * blockDim.x + threadIdx.x;
    if (t >= N * 32) return;
    int n = t >> 5, d4 = t & 31;
    ((float4*)x)[t] = ((const float4*)POI)[(size_t)idx[n] * 32 + d4];
}

// ---------------- BiSeqGCN: per-node 2-way attention ------------------------
// One warp per node.
__global__ void k_H(const float* __restrict__ x,
                    const float* __restrict__ delta,
                    const int* __restrict__ edge_dist,
                    const int* __restrict__ batch_ids,
                    const int* __restrict__ node_pos,
                    const int* __restrict__ lengths,
                    float* __restrict__ H, int N) {
    int warp = (blockIdx.x * blockDim.x + threadIdx.x) >> 5;
    int lane = threadIdx.x & 31;
    if (warp >= N) return;
    int n = warp;
    int s = batch_ids[n];
    int p = node_pos[n];
    int L = lengths[s];
    bool hf = (p > 0);
    bool hb = (p < L - 1);

    const float4* x4 = (const float4*)x;
    float4 xv  = x4[(size_t)n * 32 + lane];
    float4 wf4 = ((const float4*)g_wf)[lane];
    float4 wb4 = ((const float4*)g_wb)[lane];

    float lf = 0.f;
    if (hf) {
        int ef = n - s - 1;                 // global id of edge (n-1 -> n)
        int ed = edge_dist[ef];
        float4 dv = ((const float4*)delta)[(size_t)ed * 32 + lane];
        lf = (xv.x + dv.x) * wf4.x + (xv.y + dv.y) * wf4.y +
             (xv.z + dv.z) * wf4.z + (xv.w + dv.w) * wf4.w;
    }
    float lb = xv.x * wb4.x + xv.y * wb4.y + xv.z * wb4.z + xv.w * wb4.w;

    #pragma unroll
    for (int off = 16; off >= 1; off >>= 1) {
        lf += __shfl_xor_sync(0xffffffffu, lf, off);
        lb += __shfl_xor_sync(0xffffffffu, lb, off);
    }

    float m = -1e30f;
    if (hf) m = lf;
    if (hb) m = fmaxf(m, lb);
    float ew_f = hf ? expf(lf - m) : 0.f;
    float ew_b = hb ? expf(lb - m) : 0.f;
    float inv = 1.f / (ew_f + ew_b + 1e-16f);
    ew_f *= inv;
    ew_b *= inv;

    float4 hv = make_float4(0.f, 0.f, 0.f, 0.f);
    if (hf) {
        float4 a = x4[(size_t)(n - 1) * 32 + lane];
        hv.x += ew_f * a.x; hv.y += ew_f * a.y; hv.z += ew_f * a.z; hv.w += ew_f * a.w;
    }
    if (hb) {
        float4 a = x4[(size_t)(n + 1) * 32 + lane];
        hv.x += ew_b * a.x; hv.y += ew_b * a.y; hv.z += ew_b * a.z; hv.w += ew_b * a.w;
    }
    ((float4*)H)[(size_t)n * 32 + lane] = hv;
}

// ---------------- LayerNorm over D=128, optional residual input -------------
template <bool RES>
__global__ void k_ln(const float* __restrict__ in,
                     const float* __restrict__ res,
                     const float* __restrict__ g,
                     const float* __restrict__ b,
                     float* __restrict__ out, int N) {
    int w = (blockIdx.x * blockDim.x + threadIdx.x) >> 5;
    int lane = threadIdx.x & 31;
    if (w >= N) return;
    float4 v = ((const float4*)in)[(size_t)w * 32 + lane];
    if (RES) {
        float4 r = ((const float4*)res)[(size_t)w * 32 + lane];
        v.x += r.x; v.y += r.y; v.z += r.z; v.w += r.w;
    }
    float s = v.x + v.y + v.z + v.w;
    #pragma unroll
    for (int off = 16; off >= 1; off >>= 1) s += __shfl_xor_sync(0xffffffffu, s, off);
    float mu = s * (1.f / 128.f);
    float dx = v.x - mu, dy = v.y - mu, dz = v.z - mu, dw = v.w - mu;
    float ss = dx * dx + dy * dy + dz * dz + dw * dw;
    #pragma unroll
    for (int off = 16; off >= 1; off >>= 1) ss += __shfl_xor_sync(0xffffffffu, ss, off);
    float rstd = rsqrtf(ss * (1.f / 128.f) + 1e-8f);
    float4 gg = ((const float4*)g)[lane];
    float4 bb = ((const float4*)b)[lane];
    float4 o;
    o.x = dx * rstd * gg.x + bb.x;
    o.y = dy * rstd * gg.y + bb.y;
    o.z = dz * rstd * gg.z + bb.z;
    o.w = dw * rstd * gg.w + bb.w;
    ((float4*)out)[(size_t)w * 32 + lane] = o;
}

// ---------------- GEMM: out[M,128] = in[M,128] @ W[128,128]^T + bias --------
// Block: 256 threads = 64 column-threads x 4 row-groups; 32-row tile.
// W staged transposed in smem (conflict-free), input tile in smem (broadcast).
template <int RELU>
__global__ void gemm128(const float* __restrict__ in,
                        const float* __restrict__ W,
                        const float* __restrict__ bias,
                        float* __restrict__ out, int M) {
    extern __shared__ float sm[];
    float*  Ws   = sm;                       // [128][129] transposed: Ws[k*129+c]
    float4* in_s = (float4*)(sm + 128 * 129);  // [32 rows][32 float4]

    int tid = threadIdx.x;
    int row0 = blockIdx.x * 32;

    for (int i = tid; i < 128 * 128; i += 256) {
        int c = i >> 7, k = i & 127;
        Ws[k * 129 + c] = W[i];
    }
    for (int i = tid; i < 32 * 32; i += 256) {
        int r = i >> 5, k4 = i & 31;
        int gr = row0 + r;
        float4 v = make_float4(0.f, 0.f, 0.f, 0.f);
        if (gr < M) v = ((const float4*)in)[(size_t)gr * 32 + k4];
        in_s[r * 32 + k4] = v;
    }
    __syncthreads();

    int c  = tid & 63;   // columns c and c+64
    int rg = tid >> 6;   // rows rg*8 .. rg*8+7
    float accA[8], accB[8];
    #pragma unroll
    for (int r = 0; r < 8; r++) { accA[r] = 0.f; accB[r] = 0.f; }

    #pragma unroll 4
    for (int kk = 0; kk < 32; kk++) {
        float wa0 = Ws[(4 * kk + 0) * 129 + c];
        float wa1 = Ws[(4 * kk + 1) * 129 + c];
        float wa2 = Ws[(4 * kk + 2) * 129 + c];
        float wa3 = Ws[(4 * kk + 3) * 129 + c];
        float wb0 = Ws[(4 * kk + 0) * 129 + c + 64];
        float wb1 = Ws[(4 * kk + 1) * 129 + c + 64];
        float wb2 = Ws[(4 * kk + 2) * 129 + c + 64];
        float wb3 = Ws[(4 * kk + 3) * 129 + c + 64];
        #pragma unroll
        for (int r = 0; r < 8; r++) {
            float4 v = in_s[(rg * 8 + r) * 32 + kk];
            accA[r] += v.x * wa0 + v.y * wa1 + v.z * wa2 + v.w * wa3;
            accB[r] += v.x * wb0 + v.y * wb1 + v.z * wb2 + v.w * wb3;
        }
    }

    float ba = bias[c], bb = bias[c + 64];
    #pragma unroll
    for (int r = 0; r < 8; r++) {
        int gr = row0 + rg * 8 + r;
        if (gr < M) {
            float a = accA[r] + ba;
            float b = accB[r] + bb;
            if (RELU) { a = fmaxf(a, 0.f); b = fmaxf(b, 0.f); }
            out[(size_t)gr * 128 + c]      = a;
            out[(size_t)gr * 128 + c + 64] = b;
        }
    }
}

// ---------------- per-(session, head) attention, online softmax -------------
__global__ void k_attn(const float* __restrict__ q,
                       const float* __restrict__ k,
                       const float* __restrict__ v,
                       float* __restrict__ ctx,
                       const int* __restrict__ lengths) {
    __shared__ float Ks[MAXLEN * 32];
    __shared__ float Vs[MAXLEN * 32];
    int s = blockIdx.x, h = blockIdx.y;
    int L = lengths[s];
    int n0 = g_starts[s];
    int tid = threadIdx.x;  // 160 threads

    for (int i = tid; i < L * 32; i += MAXLEN) {
        int j = i >> 5, d = i & 31;
        size_t base = (size_t)(n0 + j) * 128 + h * 32 + d;
        Ks[i] = k[base];
        Vs[i] = v[base];
    }
    __syncthreads();
    if (tid >= L) return;

    float4 qv[8];
    const float4* q4 = (const float4*)(q + (size_t)(n0 + tid) * 128 + h * 32);
    #pragma unroll
    for (int d4 = 0; d4 < 8; d4++) qv[d4] = q4[d4];

    float m = -1e30f, l = 0.f;
    float4 acc[8];
    #pragma unroll
    for (int d4 = 0; d4 < 8; d4++) acc[d4] = make_float4(0.f, 0.f, 0.f, 0.f);

    for (int j = 0; j < L; j++) {
        const float4* K4 = (const float4*)(Ks + j * 32);
        float sc = 0.f;
        #pragma unroll
        for (int d4 = 0; d4 < 8; d4++) {
            float4 kk = K4[d4];
            sc += qv[d4].x * kk.x + qv[d4].y * kk.y + qv[d4].z * kk.z + qv[d4].w * kk.w;
        }
        sc *= 0.17677669529663687f;  // 1/sqrt(32)
        float nm = fmaxf(m, sc);
        float scale = expf(m - nm);
        float e = expf(sc - nm);
        l = l * scale + e;
        const float4* V4 = (const float4*)(Vs + j * 32);
        #pragma unroll
        for (int d4 = 0; d4 < 8; d4++) {
            float4 vv = V4[d4];
            acc[d4].x = acc[d4].x * scale + e * vv.x;
            acc[d4].y = acc[d4].y * scale + e * vv.y;
            acc[d4].z = acc[d4].z * scale + e * vv.z;
            acc[d4].w = acc[d4].w * scale + e * vv.w;
        }
        m = nm;
    }
    float invl = 1.f / l;
    float4* o = (float4*)(ctx + (size_t)(n0 + tid) * 128 + h * 32);
    #pragma unroll
    for (int d4 = 0; d4 < 8; d4++) {
        float4 a = acc[d4];
        o[d4] = make_float4(a.x * invl, a.y * invl, a.z * invl, a.w * invl);
    }
}

// ---------------- masked mean pool: S_u[s] = mean_p (a + b) -----------------
__global__ void k_pool(const float* __restrict__ a,
                       const float* __restrict__ b,
                       const int* __restrict__ lengths,
                       float* __restrict__ out) {
    int s = blockIdx.x;
    int d = threadIdx.x;  // 128
    int L = lengths[s];
    int n0 = g_starts[s];
    float sum = 0.f;
    for (int p = 0; p < L; p++) {
        size_t idx = (size_t)(n0 + p) * 128 + d;
        sum += a[idx] + b[idx];
    }
    out[(size_t)s * 128 + d] = sum / (float)L;
}

// ---------------------------------------------------------------------------
extern "C" void kernel_launch(void* const* d_in, const int* in_sizes, int n_in,
                              void* d_out, int out_size) {
    (void)n_in; (void)out_size;
    const float* POI    = (const float*)d_in[0];
    const float* delta  = (const float*)d_in[1];
    const float* attW   = (const float*)d_in[2];
    const float* a_src  = (const float*)d_in[3];
    const float* a_dst  = (const float*)d_in[4];
    const float* ipw    = (const float*)d_in[5];   // [384,128]
    const float* ipb    = (const float*)d_in[6];   // [384]
    const float* opw    = (const float*)d_in[7];
    const float* opb    = (const float*)d_in[8];
    const float* ln1g   = (const float*)d_in[9];
    const float* ln1b   = (const float*)d_in[10];
    const float* ln2g   = (const float*)d_in[11];
    const float* ln2b   = (const float*)d_in[12];
    const float* f1w    = (const float*)d_in[13];
    const float* f1b    = (const float*)d_in[14];
    const float* f2w    = (const float*)d_in[15];
    const float* f2b    = (const float*)d_in[16];
    const int* sess_idx  = (const int*)d_in[17];
    const int* edge_dist = (const int*)d_in[18];
    const int* batch_ids = (const int*)d_in[20];
    const int* node_pos  = (const int*)d_in[21];
    const int* lengths   = (const int*)d_in[22];

    int N = in_sizes[17];

    float* bx   = nullptr; cudaGetSymbolAddress((void**)&bx,   g_bufA);
    float* bH   = nullptr; cudaGetSymbolAddress((void**)&bH,   g_bufB);
    float* bQ   = nullptr; cudaGetSymbolAddress((void**)&bQ,   g_bufC);
    float* bq   = nullptr; cudaGetSymbolAddress((void**)&bq,   g_bufD);
    float* bk   = nullptr; cudaGetSymbolAddress((void**)&bk,   g_bufE);
    float* bv   = nullptr; cudaGetSymbolAddress((void**)&bv,   g_bufF);
    float* bG   = nullptr; cudaGetSymbolAddress((void**)&bG,   g_bufG);
    // aliases for reuse phases
    float* bctx  = bx;   // x dead after k_H/LN1
    float* bo    = bH;   // H dead after k/v projections
    float* bf1   = bQ;   // Q dead after LN2 residual
    float* bf2   = bq;   // q dead after attention
    float* bout2 = bG;

    size_t gsm = (128 * 129 + 32 * 32 * 4) * sizeof(float);  // 82432 B
    cudaFuncSetAttribute(gemm128<0>, cudaFuncAttributeMaxDynamicSharedMemorySize, (int)gsm);
    cudaFuncSetAttribute(gemm128<1>, cudaFuncAttributeMaxDynamicSharedMemorySize, (int)gsm);

    int wgrid = (N * 32 + 255) / 256;  // warp-per-row kernels (8 rows / 256-thread block)
    int gb = (N + 31) / 32;

    k_prep_w<<<1, 128>>>(attW, a_src, a_dst);
    k_starts<<<1, BSESS>>>(lengths);
    k_gather<<<(N * 32 + 255) / 256, 256>>>(POI, sess_idx, bx, N);
    k_H<<<wgrid, 256>>>(bx, delta, edge_dist, batch_ids, node_pos, lengths, bH, N);
    k_ln<false><<<wgrid, 256>>>(bH, nullptr, ln1g, ln1b, bQ, N);

    gemm128<0><<<gb, 256, gsm>>>(bQ, ipw,              ipb,       bq, N);
    gemm128<0><<<gb, 256, gsm>>>(bH, ipw + 128 * 128,  ipb + 128, bk, N);
    gemm128<0><<<gb, 256, gsm>>>(bH, ipw + 256 * 128,  ipb + 256, bv, N);

    k_attn<<<dim3(BSESS, 4), MAXLEN>>>(bq, bk, bv, bctx, lengths);

    gemm128<0><<<gb, 256, gsm>>>(bctx, opw, opb, bo, N);
    k_ln<true><<<wgrid, 256>>>(bo, bQ, ln2g, ln2b, bout2, N);

    gemm128<1><<<gb, 256, gsm>>>(bout2, f1w, f1b, bf1, N);
    gemm128<0><<<gb, 256, gsm>>>(bf1,   f2w, f2b, bf2, N);

    k_pool<<<BSESS, 128>>>(bout2, bf2, lengths, (float*)d_out);
}

// round 11
// speedup vs baseline: 1.4432x; 1.4432x over previous
#include <cuda_runtime.h>
#include <cuda_bf16.h>
#include <cstdint>
#include <math.h>

// ---------------------------------------------------------------------------
// SeqGraphRepNetwork on GB300: node-space + mma.sync (HMMA) GEMMs.
//  * GAT edge logits collapse to 2 precomputed 128-vectors (chain graph).
//  * All transformer math in node space (N rows, no padding).
//  * All 7 [N,128]@[128,128]^T GEMMs on tensor cores via 3-term bf16 split:
//      D = Ahi*Bhi + Ahi*Blo + Alo*Bhi   (~fp24 effective precision)
//    using mma.sync.aligned.m16n8k16 (base sm_103 target; tcgen05 is
//    sm_103a-only and this toolchain lowers through compute_103).
//  * B operand [n][k] loaded with NON-trans ldmatrix (k-contiguous pairs),
//    n8-tile pairing {r[nt&1], r[(nt&1)+2]}.
// ---------------------------------------------------------------------------

#define NMAX   116000
#define BSESS  1024
#define MAXLEN 160

__device__ float g_bufA[NMAX * 128];
__device__ float g_bufB[NMAX * 128];
__device__ float g_bufC[NMAX * 128];
__device__ float g_bufD[NMAX * 128];
__device__ float g_bufE[NMAX * 128];
__device__ float g_bufF[NMAX * 128];
__device__ float g_bufG[NMAX * 128];
__device__ float g_wf[128];
__device__ float g_wb[128];
__device__ int   g_starts[BSESS + 1];

// ======================= small prep / elementwise kernels ===================

__global__ void k_prep_w(const float* __restrict__ attW,
                         const float* __restrict__ a_src,
                         const float* __restrict__ a_dst) {
    int k = threadIdx.x;
    float f = 0.f, b = 0.f;
    for (int d = 0; d < 128; d++) {
        float w = attW[d * 128 + k];
        f += a_src[d] * w;
        b += a_dst[d] * w;
    }
    g_wf[k] = f;
    g_wb[k] = b;
}

__global__ void k_starts(const int* __restrict__ lengths) {
    __shared__ int sm[BSESS];
    int t = threadIdx.x;
    sm[t] = lengths[t];
    __syncthreads();
    for (int off = 1; off < BSESS; off <<= 1) {
        int v = (t >= off) ? sm[t - off] : 0;
        __syncthreads();
        sm[t] += v;
        __syncthreads();
    }
    g_starts[t + 1] = sm[t];
    if (t == 0) g_starts[0] = 0;
}

__global__ void k_gather(const float* __restrict__ POI,
                         const int* __restrict__ idx,
                         float* __restrict__ x, int N) {
    int t = blockIdx.x * blockDim.x + threadIdx.x;
    if (t >= N * 32) return;
    int n = t >> 5, d4 = t & 31;
    ((float4*)x)[t] = ((const float4*)POI)[(size_t)idx[n] * 32 + d4];
}

__global__ void k_H(const float* __restrict__ x,
                    const float* __restrict__ delta,
                    const int* __restrict__ edge_dist,
                    const int* __restrict__ batch_ids,
                    const int* __restrict__ node_pos,
                    const int* __restrict__ lengths,
                    float* __restrict__ H, int N) {
    int warp = (blockIdx.x * blockDim.x + threadIdx.x) >> 5;
    int lane = threadIdx.x & 31;
    if (warp >= N) return;
    int n = warp;
    int s = batch_ids[n];
    int p = node_pos[n];
    int L = lengths[s];
    bool hf = (p > 0);
    bool hb = (p < L - 1);

    const float4* x4 = (const float4*)x;
    float4 xv  = x4[(size_t)n * 32 + lane];
    float4 wf4 = ((const float4*)g_wf)[lane];
    float4 wb4 = ((const float4*)g_wb)[lane];

    float lf = 0.f;
    if (hf) {
        int ef = n - s - 1;
        int ed = edge_dist[ef];
        float4 dv = ((const float4*)delta)[(size_t)ed * 32 + lane];
        lf = (xv.x + dv.x) * wf4.x + (xv.y + dv.y) * wf4.y +
             (xv.z + dv.z) * wf4.z + (xv.w + dv.w) * wf4.w;
    }
    float lb = xv.x * wb4.x + xv.y * wb4.y + xv.z * wb4.z + xv.w * wb4.w;

    #pragma unroll
    for (int off = 16; off >= 1; off >>= 1) {
        lf += __shfl_xor_sync(0xffffffffu, lf, off);
        lb += __shfl_xor_sync(0xffffffffu, lb, off);
    }

    float m = -1e30f;
    if (hf) m = lf;
    if (hb) m = fmaxf(m, lb);
    float ew_f = hf ? expf(lf - m) : 0.f;
    float ew_b = hb ? expf(lb - m) : 0.f;
    float inv = 1.f / (ew_f + ew_b + 1e-16f);
    ew_f *= inv;
    ew_b *= inv;

    float4 hv = make_float4(0.f, 0.f, 0.f, 0.f);
    if (hf) {
        float4 a = x4[(size_t)(n - 1) * 32 + lane];
        hv.x += ew_f * a.x; hv.y += ew_f * a.y; hv.z += ew_f * a.z; hv.w += ew_f * a.w;
    }
    if (hb) {
        float4 a = x4[(size_t)(n + 1) * 32 + lane];
        hv.x += ew_b * a.x; hv.y += ew_b * a.y; hv.z += ew_b * a.z; hv.w += ew_b * a.w;
    }
    ((float4*)H)[(size_t)n * 32 + lane] = hv;
}

template <bool RES>
__global__ void k_ln(const float* __restrict__ in,
                     const float* __restrict__ res,
                     const float* __restrict__ g,
                     const float* __restrict__ b,
                     float* __restrict__ out, int N) {
    int w = (blockIdx.x * blockDim.x + threadIdx.x) >> 5;
    int lane = threadIdx.x & 31;
    if (w >= N) return;
    float4 v = ((const float4*)in)[(size_t)w * 32 + lane];
    if (RES) {
        float4 r = ((const float4*)res)[(size_t)w * 32 + lane];
        v.x += r.x; v.y += r.y; v.z += r.z; v.w += r.w;
    }
    float s = v.x + v.y + v.z + v.w;
    #pragma unroll
    for (int off = 16; off >= 1; off >>= 1) s += __shfl_xor_sync(0xffffffffu, s, off);
    float mu = s * (1.f / 128.f);
    float dx = v.x - mu, dy = v.y - mu, dz = v.z - mu, dw = v.w - mu;
    float ss = dx * dx + dy * dy + dz * dz + dw * dw;
    #pragma unroll
    for (int off = 16; off >= 1; off >>= 1) ss += __shfl_xor_sync(0xffffffffu, ss, off);
    float rstd = rsqrtf(ss * (1.f / 128.f) + 1e-8f);
    float4 gg = ((const float4*)g)[lane];
    float4 bb = ((const float4*)b)[lane];
    float4 o;
    o.x = dx * rstd * gg.x + bb.x;
    o.y = dy * rstd * gg.y + bb.y;
    o.z = dz * rstd * gg.z + bb.z;
    o.w = dw * rstd * gg.w + bb.w;
    ((float4*)out)[(size_t)w * 32 + lane] = o;
}

// =========================== mma.sync GEMM ==================================
// out[M,128] = in[M,128] @ W[128,128]^T + bias  (relu flag)
// Block: 256 threads, tile 128 rows x 128 cols, K = 128.
// SMEM: A hi/lo + W hi/lo as bf16 [128][136] (stride 136 => conflict-free
// ldmatrix). Warp w: rows (w&3)*32 .. +31, cols (w>>2)*64 .. +63.

#define LDSTRIDE 136
#define SM_AH 0
#define SM_AL 34816
#define SM_WH 69632
#define SM_WL 104448
#define SM_TOTAL 139264

__device__ __forceinline__ uint32_t smem_to_u32(const void* smem_ptr) {
    uint32_t addr;
    asm("{ .reg .u64 tmp; cvta.to.shared.u64 tmp, %1; cvt.u32.u64 %0, tmp; }"
        : "=r"(addr) : "l"(smem_ptr));
    return addr;
}

#define LDMATRIX_X4(r, addr) \
    asm volatile("ldmatrix.sync.aligned.m8n8.x4.shared.b16 {%0,%1,%2,%3}, [%4];" \
        : "=r"((r)[0]), "=r"((r)[1]), "=r"((r)[2]), "=r"((r)[3]) : "r"(addr))

#define MMA16816(c, a, b0, b1) \
    asm volatile("mma.sync.aligned.m16n8k16.row.col.f32.bf16.bf16.f32 " \
        "{%0,%1,%2,%3}, {%4,%5,%6,%7}, {%8,%9}, {%0,%1,%2,%3};" \
        : "+f"((c)[0]), "+f"((c)[1]), "+f"((c)[2]), "+f"((c)[3]) \
        : "r"((a)[0]), "r"((a)[1]), "r"((a)[2]), "r"((a)[3]), \
          "r"(b0), "r"(b1))

__device__ __forceinline__ unsigned pack2_bf16(float a, float b) {
    __nv_bfloat162 t = __floats2bfloat162_rn(a, b);
    return *(unsigned*)&t;
}

__device__ __forceinline__ void cvt_hilo(float4 v0, float4 v1,
                                         uint4* hi, uint4* lo) {
    float e0 = v0.x, e1 = v0.y, e2 = v0.z, e3 = v0.w;
    float e4 = v1.x, e5 = v1.y, e6 = v1.z, e7 = v1.w;
    hi->x = pack2_bf16(e0, e1);
    hi->y = pack2_bf16(e2, e3);
    hi->z = pack2_bf16(e4, e5);
    hi->w = pack2_bf16(e6, e7);
    float r0 = e0 - __bfloat162float(__float2bfloat16_rn(e0));
    float r1 = e1 - __bfloat162float(__float2bfloat16_rn(e1));
    float r2 = e2 - __bfloat162float(__float2bfloat16_rn(e2));
    float r3 = e3 - __bfloat162float(__float2bfloat16_rn(e3));
    float r4 = e4 - __bfloat162float(__float2bfloat16_rn(e4));
    float r5 = e5 - __bfloat162float(__float2bfloat16_rn(e5));
    float r6 = e6 - __bfloat162float(__float2bfloat16_rn(e6));
    float r7 = e7 - __bfloat162float(__float2bfloat16_rn(e7));
    lo->x = pack2_bf16(r0, r1);
    lo->y = pack2_bf16(r2, r3);
    lo->z = pack2_bf16(r4, r5);
    lo->w = pack2_bf16(r6, r7);
}

__global__ void __launch_bounds__(256, 1)
gemm_mma(const float* __restrict__ in,
         const float* __restrict__ W,
         const float* __restrict__ bias,
         float* __restrict__ out, int M, int relu) {
    extern __shared__ char smem[];
    int tid = threadIdx.x;
    int wid = tid >> 5;
    int lane = tid & 31;
    int row0 = blockIdx.x * 128;
    int rows = M - row0;
    if (rows > 128) rows = 128;

    // Stage A (hi/lo) at [row][k], stride LDSTRIDE bf16
    for (int i = tid; i < 2048; i += 256) {
        int row = i >> 4;
        int k0 = (i & 15) * 8;
        float4 v0 = make_float4(0.f, 0.f, 0.f, 0.f);
        float4 v1 = v0;
        if (row < rows) {
            const float4* p = (const float4*)(in + (size_t)(row0 + row) * 128 + k0);
            v0 = p[0];
            v1 = p[1];
        }
        uint4 hi, lo;
        cvt_hilo(v0, v1, &hi, &lo);
        size_t off = (size_t)(row * LDSTRIDE + k0) * 2;
        *(uint4*)(smem + SM_AH + off) = hi;
        *(uint4*)(smem + SM_AL + off) = lo;
    }
    // Stage W (hi/lo) at [col][k]  (W input is [col][k] row-major already)
    for (int i = tid; i < 2048; i += 256) {
        int row = i >> 4;
        int k0 = (i & 15) * 8;
        const float4* p = (const float4*)(W + (size_t)row * 128 + k0);
        float4 v0 = p[0];
        float4 v1 = p[1];
        uint4 hi, lo;
        cvt_hilo(v0, v1, &hi, &lo);
        size_t off = (size_t)(row * LDSTRIDE + k0) * 2;
        *(uint4*)(smem + SM_WH + off) = hi;
        *(uint4*)(smem + SM_WL + off) = lo;
    }
    __syncthreads();

    uint32_t sbase = smem_to_u32(smem);
    int wr = (wid & 3) * 32;   // warp row base
    int wc = (wid >> 2) * 64;  // warp col base

    float c[2][8][4];
    #pragma unroll
    for (int rt = 0; rt < 2; rt++)
        #pragma unroll
        for (int nt = 0; nt < 8; nt++)
            #pragma unroll
            for (int j = 0; j < 4; j++) c[rt][nt][j] = 0.f;

    // A ldmatrix: rows (lane&15), k chunk (lane>>4)*8  -> frag regs
    //   r0 = rows0-7/k0-7, r1 = rows8-15/k0-7, r2 = rows0-7/k8-15, r3 = rows8-15/k8-15
    int a_row = wr + (lane & 15);
    int a_kh  = (lane >> 4) * 8;
    uint32_t offA0 = (uint32_t)(a_row * LDSTRIDE + a_kh) * 2;
    uint32_t offA1 = offA0 + (uint32_t)(16 * LDSTRIDE * 2);
    // B ldmatrix (NON-trans: smem is [n][k], fragment wants k-contiguous pairs):
    //   rows n = base+(lane&15), k chunk (lane>>4)*8
    //   r0 = n0-7/k0-7, r1 = n8-15/k0-7, r2 = n0-7/k8-15, r3 = n8-15/k8-15
    int b_n  = lane & 15;
    int b_kh = (lane >> 4) * 8;

    #pragma unroll
    for (int ks = 0; ks < 8; ks++) {
        uint32_t kbyte = (uint32_t)(ks * 16 * 2);
        uint32_t ah0[4], ah1[4], al0[4], al1[4];
        LDMATRIX_X4(ah0, sbase + SM_AH + offA0 + kbyte);
        LDMATRIX_X4(ah1, sbase + SM_AH + offA1 + kbyte);
        LDMATRIX_X4(al0, sbase + SM_AL + offA0 + kbyte);
        LDMATRIX_X4(al1, sbase + SM_AL + offA1 + kbyte);

        uint32_t bh[4][4], bl[4][4];
        #pragma unroll
        for (int nt2 = 0; nt2 < 4; nt2++) {
            uint32_t offB = (uint32_t)((wc + nt2 * 16 + b_n) * LDSTRIDE + b_kh) * 2;
            LDMATRIX_X4(bh[nt2], sbase + SM_WH + offB + kbyte);
            LDMATRIX_X4(bl[nt2], sbase + SM_WL + offB + kbyte);
        }

        #pragma unroll
        for (int nt = 0; nt < 8; nt++) {
            int nt2 = nt >> 1;
            int sel = nt & 1;            // n8 tile: low(0)->regs {0,2}, high(1)->{1,3}
            uint32_t bh0 = bh[nt2][sel],     bh1 = bh[nt2][sel + 2];
            uint32_t bl0 = bl[nt2][sel],     bl1 = bl[nt2][sel + 2];
            MMA16816(c[0][nt], ah0, bh0, bh1);
            MMA16816(c[0][nt], ah0, bl0, bl1);
            MMA16816(c[0][nt], al0, bh0, bh1);
            MMA16816(c[1][nt], ah1, bh0, bh1);
            MMA16816(c[1][nt], ah1, bl0, bl1);
            MMA16816(c[1][nt], al1, bh0, bh1);
        }
    }

    // Epilogue: write fragments directly to global
    int r_in = lane >> 2;            // 0..7
    int cpair = (lane & 3) * 2;
    #pragma unroll
    for (int nt = 0; nt < 8; nt++) {
        int col = wc + nt * 8 + cpair;
        float2 b2 = *(const float2*)(bias + col);
        #pragma unroll
        for (int rt = 0; rt < 2; rt++) {
            int rA = wr + rt * 16 + r_in;
            int rB = rA + 8;
            float d0 = c[rt][nt][0] + b2.x;
            float d1 = c[rt][nt][1] + b2.y;
            float d2 = c[rt][nt][2] + b2.x;
            float d3 = c[rt][nt][3] + b2.y;
            if (relu) {
                d0 = fmaxf(d0, 0.f); d1 = fmaxf(d1, 0.f);
                d2 = fmaxf(d2, 0.f); d3 = fmaxf(d3, 0.f);
            }
            if (rA < rows) {
                float2 v; v.x = d0; v.y = d1;
                *(float2*)(out + (size_t)(row0 + rA) * 128 + col) = v;
            }
            if (rB < rows) {
                float2 v; v.x = d2; v.y = d3;
                *(float2*)(out + (size_t)(row0 + rB) * 128 + col) = v;
            }
        }
    }
}

// ======================= attention + pool (fp32) ============================

__global__ void k_attn(const float* __restrict__ q,
                       const float* __restrict__ k,
                       const float* __restrict__ v,
                       float* __restrict__ ctx,
                       const int* __restrict__ lengths) {
    __shared__ float Ks[MAXLEN * 32];
    __shared__ float Vs[MAXLEN * 32];
    int s = blockIdx.x, h = blockIdx.y;
    int L = lengths[s];
    int n0 = g_starts[s];
    int tid = threadIdx.x;

    for (int i = tid; i < L * 32; i += MAXLEN) {
        int j = i >> 5, d = i & 31;
        size_t base = (size_t)(n0 + j) * 128 + h * 32 + d;
        Ks[i] = k[base];
        Vs[i] = v[base];
    }
    __syncthreads();
    if (tid >= L) return;

    float4 qv[8];
    const float4* q4 = (const float4*)(q + (size_t)(n0 + tid) * 128 + h * 32);
    #pragma unroll
    for (int d4 = 0; d4 < 8; d4++) qv[d4] = q4[d4];

    float m = -1e30f, l = 0.f;
    float4 acc[8];
    #pragma unroll
    for (int d4 = 0; d4 < 8; d4++) acc[d4] = make_float4(0.f, 0.f, 0.f, 0.f);

    for (int j = 0; j < L; j++) {
        const float4* K4 = (const float4*)(Ks + j * 32);
        float sc = 0.f;
        #pragma unroll
        for (int d4 = 0; d4 < 8; d4++) {
            float4 kk = K4[d4];
            sc += qv[d4].x * kk.x + qv[d4].y * kk.y + qv[d4].z * kk.z + qv[d4].w * kk.w;
        }
        sc *= 0.17677669529663687f;
        float nm = fmaxf(m, sc);
        float scale = expf(m - nm);
        float e = expf(sc - nm);
        l = l * scale + e;
        const float4* V4 = (const float4*)(Vs + j * 32);
        #pragma unroll
        for (int d4 = 0; d4 < 8; d4++) {
            float4 vv = V4[d4];
            acc[d4].x = acc[d4].x * scale + e * vv.x;
            acc[d4].y = acc[d4].y * scale + e * vv.y;
            acc[d4].z = acc[d4].z * scale + e * vv.z;
            acc[d4].w = acc[d4].w * scale + e * vv.w;
        }
        m = nm;
    }
    float invl = 1.f / l;
    float4* o = (float4*)(ctx + (size_t)(n0 + tid) * 128 + h * 32);
    #pragma unroll
    for (int d4 = 0; d4 < 8; d4++) {
        float4 a = acc[d4];
        o[d4] = make_float4(a.x * invl, a.y * invl, a.z * invl, a.w * invl);
    }
}

__global__ void k_pool(const float* __restrict__ a,
                       const float* __restrict__ b,
                       const int* __restrict__ lengths,
                       float* __restrict__ out) {
    int s = blockIdx.x;
    int d = threadIdx.x;
    int L = lengths[s];
    int n0 = g_starts[s];
    float sum = 0.f;
    for (int p = 0; p < L; p++) {
        size_t idx = (size_t)(n0 + p) * 128 + d;
        sum += a[idx] + b[idx];
    }
    out[(size_t)s * 128 + d] = sum / (float)L;
}

// ---------------------------------------------------------------------------
extern "C" void kernel_launch(void* const* d_in, const int* in_sizes, int n_in,
                              void* d_out, int out_size) {
    (void)n_in; (void)out_size;
    const float* POI    = (const float*)d_in[0];
    const float* delta  = (const float*)d_in[1];
    const float* attW   = (const float*)d_in[2];
    const float* a_src  = (const float*)d_in[3];
    const float* a_dst  = (const float*)d_in[4];
    const float* ipw    = (const float*)d_in[5];
    const float* ipb    = (const float*)d_in[6];
    const float* opw    = (const float*)d_in[7];
    const float* opb    = (const float*)d_in[8];
    const float* ln1g   = (const float*)d_in[9];
    const float* ln1b   = (const float*)d_in[10];
    const float* ln2g   = (const float*)d_in[11];
    const float* ln2b   = (const float*)d_in[12];
    const float* f1w    = (const float*)d_in[13];
    const float* f1b    = (const float*)d_in[14];
    const float* f2w    = (const float*)d_in[15];
    const float* f2b    = (const float*)d_in[16];
    const int* sess_idx  = (const int*)d_in[17];
    const int* edge_dist = (const int*)d_in[18];
    const int* batch_ids = (const int*)d_in[20];
    const int* node_pos  = (const int*)d_in[21];
    const int* lengths   = (const int*)d_in[22];

    int N = in_sizes[17];

    float* bx = nullptr; cudaGetSymbolAddress((void**)&bx, g_bufA);
    float* bH = nullptr; cudaGetSymbolAddress((void**)&bH, g_bufB);
    float* bQ = nullptr; cudaGetSymbolAddress((void**)&bQ, g_bufC);
    float* bq = nullptr; cudaGetSymbolAddress((void**)&bq, g_bufD);
    float* bk = nullptr; cudaGetSymbolAddress((void**)&bk, g_bufE);
    float* bv = nullptr; cudaGetSymbolAddress((void**)&bv, g_bufF);
    float* bG = nullptr; cudaGetSymbolAddress((void**)&bG, g_bufG);
    float* bctx  = bx;
    float* bo    = bH;
    float* bf1   = bQ;
    float* bf2   = bq;
    float* bout2 = bG;

    cudaFuncSetAttribute(gemm_mma, cudaFuncAttributeMaxDynamicSharedMemorySize, SM_TOTAL);

    int wgrid = (N * 32 + 255) / 256;
    int gb = (N + 127) / 128;

    k_prep_w<<<1, 128>>>(attW, a_src, a_dst);
    k_starts<<<1, BSESS>>>(lengths);
    k_gather<<<(N * 32 + 255) / 256, 256>>>(POI, sess_idx, bx, N);
    k_H<<<wgrid, 256>>>(bx, delta, edge_dist, batch_ids, node_pos, lengths, bH, N);
    k_ln<false><<<wgrid, 256>>>(bH, nullptr, ln1g, ln1b, bQ, N);

    gemm_mma<<<gb, 256, SM_TOTAL>>>(bQ, ipw,             ipb,       bq, N, 0);
    gemm_mma<<<gb, 256, SM_TOTAL>>>(bH, ipw + 128 * 128, ipb + 128, bk, N, 0);
    gemm_mma<<<gb, 256, SM_TOTAL>>>(bH, ipw + 256 * 128, ipb + 256, bv, N, 0);

    k_attn<<<dim3(BSESS, 4), MAXLEN>>>(bq, bk, bv, bctx, lengths);

    gemm_mma<<<gb, 256, SM_TOTAL>>>(bctx, opw, opb, bo, N, 0);
    k_ln<true><<<wgrid, 256>>>(bo, bQ, ln2g, ln2b, bout2, N);

    gemm_mma<<<gb, 256, SM_TOTAL>>>(bout2, f1w, f1b, bf1, N, 1);
    gemm_mma<<<gb, 256, SM_TOTAL>>>(bf1,   f2w, f2b, bf2, N, 0);

    k_pool<<<BSESS, 128>>>(bout2, bf2, lengths, (float*)d_out);
}

// round 12
// speedup vs baseline: 1.5498x; 1.0738x over previous
#include <cuda_runtime.h>
#include <cuda_bf16.h>
#include <cstdint>
#include <math.h>

// ---------------------------------------------------------------------------
// SeqGraphRepNetwork on GB300: node-space + mma.sync (HMMA) GEMMs.
//  R12: fusion sweep — gather+GAT+LN1 fused; K/V projections share A staging;
//  FFN2 residual fused into gemm epilogue; 1-exp online softmax in attention.
// ---------------------------------------------------------------------------

#define NMAX   116000
#define BSESS  1024
#define MAXLEN 160

__device__ float g_bufA[NMAX * 128];
__device__ float g_bufB[NMAX * 128];
__device__ float g_bufC[NMAX * 128];
__device__ float g_bufD[NMAX * 128];
__device__ float g_bufE[NMAX * 128];
__device__ float g_bufF[NMAX * 128];
__device__ float g_bufG[NMAX * 128];
__device__ float g_wf[128];
__device__ float g_wb[128];
__device__ int   g_starts[BSESS + 1];

// ======================= combined prep kernel ===============================
// block 0: w_f = a_src @ att_W, w_b = a_dst @ att_W   (128 active threads)
// block 1: inclusive scan of lengths -> g_starts       (1024 threads)

__global__ void k_prep(const float* __restrict__ attW,
                       const float* __restrict__ a_src,
                       const float* __restrict__ a_dst,
                       const int* __restrict__ lengths) {
    if (blockIdx.x == 0) {
        int k = threadIdx.x;
        if (k < 128) {
            float f = 0.f, b = 0.f;
            for (int d = 0; d < 128; d++) {
                float w = attW[d * 128 + k];
                f += a_src[d] * w;
                b += a_dst[d] * w;
            }
            g_wf[k] = f;
            g_wb[k] = b;
        }
    } else {
        __shared__ int sm[BSESS];
        int t = threadIdx.x;
        sm[t] = lengths[t];
        __syncthreads();
        for (int off = 1; off < BSESS; off <<= 1) {
            int v = (t >= off) ? sm[t - off] : 0;
            __syncthreads();
            sm[t] += v;
            __syncthreads();
        }
        g_starts[t + 1] = sm[t];
        if (t == 0) g_starts[0] = 0;
    }
}

// ============ fused: POI gather + BiSeqGCN + LayerNorm1 =====================
// One warp per node. POI table (25.6MB) fits in L2 -> neighbor gathers are
// L2 hits; avoids materializing x[N,128] entirely.

__global__ void k_hg(const float* __restrict__ POI,
                     const float* __restrict__ delta,
                     const int* __restrict__ sess_idx,
                     const int* __restrict__ edge_dist,
                     const int* __restrict__ batch_ids,
                     const int* __restrict__ node_pos,
                     const int* __restrict__ lengths,
                     const float* __restrict__ ln1g,
                     const float* __restrict__ ln1b,
                     float* __restrict__ H,
                     float* __restrict__ Q, int N) {
    int n = (blockIdx.x * blockDim.x + threadIdx.x) >> 5;
    int lane = threadIdx.x & 31;
    if (n >= N) return;
    int s = batch_ids[n];
    int p = node_pos[n];
    int L = lengths[s];
    bool hf = (p > 0);
    bool hb = (p < L - 1);

    const float4* POI4 = (const float4*)POI;
    float4 xv  = POI4[(size_t)sess_idx[n] * 32 + lane];
    float4 wf4 = ((const float4*)g_wf)[lane];
    float4 wb4 = ((const float4*)g_wb)[lane];

    float lf = 0.f;
    if (hf) {
        int ed = edge_dist[n - s - 1];
        float4 dv = ((const float4*)delta)[(size_t)ed * 32 + lane];
        lf = (xv.x + dv.x) * wf4.x + (xv.y + dv.y) * wf4.y +
             (xv.z + dv.z) * wf4.z + (xv.w + dv.w) * wf4.w;
    }
    float lb = xv.x * wb4.x + xv.y * wb4.y + xv.z * wb4.z + xv.w * wb4.w;

    #pragma unroll
    for (int off = 16; off >= 1; off >>= 1) {
        lf += __shfl_xor_sync(0xffffffffu, lf, off);
        lb += __shfl_xor_sync(0xffffffffu, lb, off);
    }

    float m = -1e30f;
    if (hf) m = lf;
    if (hb) m = fmaxf(m, lb);
    float ew_f = hf ? expf(lf - m) : 0.f;
    float ew_b = hb ? expf(lb - m) : 0.f;
    float inv = 1.f / (ew_f + ew_b + 1e-16f);
    ew_f *= inv;
    ew_b *= inv;

    float4 hv = make_float4(0.f, 0.f, 0.f, 0.f);
    if (hf) {
        float4 a = POI4[(size_t)sess_idx[n - 1] * 32 + lane];
        hv.x += ew_f * a.x; hv.y += ew_f * a.y; hv.z += ew_f * a.z; hv.w += ew_f * a.w;
    }
    if (hb) {
        float4 a = POI4[(size_t)sess_idx[n + 1] * 32 + lane];
        hv.x += ew_b * a.x; hv.y += ew_b * a.y; hv.z += ew_b * a.z; hv.w += ew_b * a.w;
    }
    ((float4*)H)[(size_t)n * 32 + lane] = hv;

    // ---- LayerNorm1 on hv (row is resident in the warp) ----
    float sm = hv.x + hv.y + hv.z + hv.w;
    #pragma unroll
    for (int off = 16; off >= 1; off >>= 1) sm += __shfl_xor_sync(0xffffffffu, sm, off);
    float mu = sm * (1.f / 128.f);
    float dx = hv.x - mu, dy = hv.y - mu, dz = hv.z - mu, dw = hv.w - mu;
    float ss = dx * dx + dy * dy + dz * dz + dw * dw;
    #pragma unroll
    for (int off = 16; off >= 1; off >>= 1) ss += __shfl_xor_sync(0xffffffffu, ss, off);
    float rstd = rsqrtf(ss * (1.f / 128.f) + 1e-8f);
    float4 gg = ((const float4*)ln1g)[lane];
    float4 bb = ((const float4*)ln1b)[lane];
    float4 o;
    o.x = dx * rstd * gg.x + bb.x;
    o.y = dy * rstd * gg.y + bb.y;
    o.z = dz * rstd * gg.z + bb.z;
    o.w = dw * rstd * gg.w + bb.w;
    ((float4*)Q)[(size_t)n * 32 + lane] = o;
}

// ---------------- LayerNorm with residual (LN2) -----------------------------
__global__ void k_ln(const float* __restrict__ in,
                     const float* __restrict__ res,
                     const float* __restrict__ g,
                     const float* __restrict__ b,
                     float* __restrict__ out, int N) {
    int w = (blockIdx.x * blockDim.x + threadIdx.x) >> 5;
    int lane = threadIdx.x & 31;
    if (w >= N) return;
    float4 v = ((const float4*)in)[(size_t)w * 32 + lane];
    float4 r = ((const float4*)res)[(size_t)w * 32 + lane];
    v.x += r.x; v.y += r.y; v.z += r.z; v.w += r.w;
    float s = v.x + v.y + v.z + v.w;
    #pragma unroll
    for (int off = 16; off >= 1; off >>= 1) s += __shfl_xor_sync(0xffffffffu, s, off);
    float mu = s * (1.f / 128.f);
    float dx = v.x - mu, dy = v.y - mu, dz = v.z - mu, dw = v.w - mu;
    float ss = dx * dx + dy * dy + dz * dz + dw * dw;
    #pragma unroll
    for (int off = 16; off >= 1; off >>= 1) ss += __shfl_xor_sync(0xffffffffu, ss, off);
    float rstd = rsqrtf(ss * (1.f / 128.f) + 1e-8f);
    float4 gg = ((const float4*)g)[lane];
    float4 bb = ((const float4*)b)[lane];
    float4 o;
    o.x = dx * rstd * gg.x + bb.x;
    o.y = dy * rstd * gg.y + bb.y;
    o.z = dz * rstd * gg.z + bb.z;
    o.w = dw * rstd * gg.w + bb.w;
    ((float4*)out)[(size_t)w * 32 + lane] = o;
}

// =========================== mma.sync GEMM ==================================

#define LDSTRIDE 136
#define SM_AH 0
#define SM_AL 34816
#define SM_WH 69632
#define SM_WL 104448
#define SM_TOTAL 139264

__device__ __forceinline__ uint32_t smem_to_u32(const void* smem_ptr) {
    uint32_t addr;
    asm("{ .reg .u64 tmp; cvta.to.shared.u64 tmp, %1; cvt.u32.u64 %0, tmp; }"
        : "=r"(addr) : "l"(smem_ptr));
    return addr;
}

#define LDMATRIX_X4(r, addr) \
    asm volatile("ldmatrix.sync.aligned.m8n8.x4.shared.b16 {%0,%1,%2,%3}, [%4];" \
        : "=r"((r)[0]), "=r"((r)[1]), "=r"((r)[2]), "=r"((r)[3]) : "r"(addr))

#define MMA16816(c, a, b0, b1) \
    asm volatile("mma.sync.aligned.m16n8k16.row.col.f32.bf16.bf16.f32 " \
        "{%0,%1,%2,%3}, {%4,%5,%6,%7}, {%8,%9}, {%0,%1,%2,%3};" \
        : "+f"((c)[0]), "+f"((c)[1]), "+f"((c)[2]), "+f"((c)[3]) \
        : "r"((a)[0]), "r"((a)[1]), "r"((a)[2]), "r"((a)[3]), \
          "r"(b0), "r"(b1))

__device__ __forceinline__ unsigned pack2_bf16(float a, float b) {
    __nv_bfloat162 t = __floats2bfloat162_rn(a, b);
    return *(unsigned*)&t;
}

__device__ __forceinline__ void cvt_hilo(float4 v0, float4 v1,
                                         uint4* hi, uint4* lo) {
    float e0 = v0.x, e1 = v0.y, e2 = v0.z, e3 = v0.w;
    float e4 = v1.x, e5 = v1.y, e6 = v1.z, e7 = v1.w;
    hi->x = pack2_bf16(e0, e1);
    hi->y = pack2_bf16(e2, e3);
    hi->z = pack2_bf16(e4, e5);
    hi->w = pack2_bf16(e6, e7);
    float r0 = e0 - __bfloat162float(__float2bfloat16_rn(e0));
    float r1 = e1 - __bfloat162float(__float2bfloat16_rn(e1));
    float r2 = e2 - __bfloat162float(__float2bfloat16_rn(e2));
    float r3 = e3 - __bfloat162float(__float2bfloat16_rn(e3));
    float r4 = e4 - __bfloat162float(__float2bfloat16_rn(e4));
    float r5 = e5 - __bfloat162float(__float2bfloat16_rn(e5));
    float r6 = e6 - __bfloat162float(__float2bfloat16_rn(e6));
    float r7 = e7 - __bfloat162float(__float2bfloat16_rn(e7));
    lo->x = pack2_bf16(r0, r1);
    lo->y = pack2_bf16(r2, r3);
    lo->z = pack2_bf16(r4, r5);
    lo->w = pack2_bf16(r6, r7);
}

// Stage a [rows<=128, 128] fp32 tile into hi/lo bf16 smem, stride LDSTRIDE.
__device__ __forceinline__ void stage_opnd(const float* __restrict__ src,
                                           int rows, char* smem,
                                           int off_h, int off_l, int tid) {
    for (int i = tid; i < 2048; i += 256) {
        int row = i >> 4;
        int k0 = (i & 15) * 8;
        float4 v0 = make_float4(0.f, 0.f, 0.f, 0.f);
        float4 v1 = v0;
        if (row < rows) {
            const float4* p = (const float4*)(src + (size_t)row * 128 + k0);
            v0 = p[0];
            v1 = p[1];
        }
        uint4 hi, lo;
        cvt_hilo(v0, v1, &hi, &lo);
        size_t off = (size_t)(row * LDSTRIDE + k0) * 2;
        *(uint4*)(smem + off_h + off) = hi;
        *(uint4*)(smem + off_l + off) = lo;
    }
}

// Per-warp 3-term bf16-split MMA over the staged tiles.
__device__ __forceinline__ void mma_compute(uint32_t sbase, int wid, int lane,
                                            float c[2][8][4]) {
    int wr = (wid & 3) * 32;
    int wc = (wid >> 2) * 64;
    #pragma unroll
    for (int rt = 0; rt < 2; rt++)
        #pragma unroll
        for (int nt = 0; nt < 8; nt++)
            #pragma unroll
            for (int j = 0; j < 4; j++) c[rt][nt][j] = 0.f;

    int a_row = wr + (lane & 15);
    int a_kh  = (lane >> 4) * 8;
    uint32_t offA0 = (uint32_t)(a_row * LDSTRIDE + a_kh) * 2;
    uint32_t offA1 = offA0 + (uint32_t)(16 * LDSTRIDE * 2);
    int b_n  = lane & 15;
    int b_kh = (lane >> 4) * 8;

    #pragma unroll
    for (int ks = 0; ks < 8; ks++) {
        uint32_t kbyte = (uint32_t)(ks * 16 * 2);
        uint32_t ah0[4], ah1[4], al0[4], al1[4];
        LDMATRIX_X4(ah0, sbase + SM_AH + offA0 + kbyte);
        LDMATRIX_X4(ah1, sbase + SM_AH + offA1 + kbyte);
        LDMATRIX_X4(al0, sbase + SM_AL + offA0 + kbyte);
        LDMATRIX_X4(al1, sbase + SM_AL + offA1 + kbyte);

        uint32_t bh[4][4], bl[4][4];
        #pragma unroll
        for (int nt2 = 0; nt2 < 4; nt2++) {
            uint32_t offB = (uint32_t)((wc + nt2 * 16 + b_n) * LDSTRIDE + b_kh) * 2;
            LDMATRIX_X4(bh[nt2], sbase + SM_WH + offB + kbyte);
            LDMATRIX_X4(bl[nt2], sbase + SM_WL + offB + kbyte);
        }

        #pragma unroll
        for (int nt = 0; nt < 8; nt++) {
            int nt2 = nt >> 1;
            int sel = nt & 1;
            uint32_t bh0 = bh[nt2][sel], bh1 = bh[nt2][sel + 2];
            uint32_t bl0 = bl[nt2][sel], bl1 = bl[nt2][sel + 2];
            MMA16816(c[0][nt], ah0, bh0, bh1);
            MMA16816(c[0][nt], ah0, bl0, bl1);
            MMA16816(c[0][nt], al0, bh0, bh1);
            MMA16816(c[1][nt], ah1, bh0, bh1);
            MMA16816(c[1][nt], ah1, bl0, bl1);
            MMA16816(c[1][nt], al1, bh0, bh1);
        }
    }
}

__device__ __forceinline__ void epilogue_store(float c[2][8][4],
                                               const float* __restrict__ bias,
                                               const float* __restrict__ res,
                                               float* __restrict__ out,
                                               int row0, int rows, int relu,
                                               int wid, int lane) {
    int wr = (wid & 3) * 32;
    int wc = (wid >> 2) * 64;
    int r_in = lane >> 2;
    int cpair = (lane & 3) * 2;
    #pragma unroll
    for (int nt = 0; nt < 8; nt++) {
        int col = wc + nt * 8 + cpair;
        float2 b2 = *(const float2*)(bias + col);
        #pragma unroll
        for (int rt = 0; rt < 2; rt++) {
            int rA = wr + rt * 16 + r_in;
            int rB = rA + 8;
            float d0 = c[rt][nt][0] + b2.x;
            float d1 = c[rt][nt][1] + b2.y;
            float d2 = c[rt][nt][2] + b2.x;
            float d3 = c[rt][nt][3] + b2.y;
            if (relu) {
                d0 = fmaxf(d0, 0.f); d1 = fmaxf(d1, 0.f);
                d2 = fmaxf(d2, 0.f); d3 = fmaxf(d3, 0.f);
            }
            if (rA < rows) {
                if (res) {
                    float2 rr = *(const float2*)(res + (size_t)(row0 + rA) * 128 + col);
                    d0 += rr.x; d1 += rr.y;
                }
                float2 v; v.x = d0; v.y = d1;
                *(float2*)(out + (size_t)(row0 + rA) * 128 + col) = v;
            }
            if (rB < rows) {
                if (res) {
                    float2 rr = *(const float2*)(res + (size_t)(row0 + rB) * 128 + col);
                    d2 += rr.x; d3 += rr.y;
                }
                float2 v; v.x = d2; v.y = d3;
                *(float2*)(out + (size_t)(row0 + rB) * 128 + col) = v;
            }
        }
    }
}

__global__ void __launch_bounds__(256, 1)
gemm_mma(const float* __restrict__ in,
         const float* __restrict__ W,
         const float* __restrict__ bias,
         const float* __restrict__ res,
         float* __restrict__ out, int M, int relu) {
    extern __shared__ char smem[];
    int tid = threadIdx.x;
    int wid = tid >> 5;
    int lane = tid & 31;
    int row0 = blockIdx.x * 128;
    int rows = M - row0;
    if (rows > 128) rows = 128;

    stage_opnd(in + (size_t)row0 * 128, rows, smem, SM_AH, SM_AL, tid);
    stage_opnd(W, 128, smem, SM_WH, SM_WL, tid);
    __syncthreads();

    uint32_t sbase = smem_to_u32(smem);
    float c[2][8][4];
    mma_compute(sbase, wid, lane, c);
    epilogue_store(c, bias, res, out, row0, rows, relu, wid, lane);
}

// K and V projections share one A staging (same input bH).
__global__ void __launch_bounds__(256, 1)
gemm_kv(const float* __restrict__ in,
        const float* __restrict__ Wk, const float* __restrict__ bk,
        const float* __restrict__ Wv, const float* __restrict__ bv,
        float* __restrict__ outk, float* __restrict__ outv, int M) {
    extern __shared__ char smem[];
    int tid = threadIdx.x;
    int wid = tid >> 5;
    int lane = tid & 31;
    int row0 = blockIdx.x * 128;
    int rows = M - row0;
    if (rows > 128) rows = 128;

    stage_opnd(in + (size_t)row0 * 128, rows, smem, SM_AH, SM_AL, tid);
    uint32_t sbase = smem_to_u32(smem);
    float c[2][8][4];

    stage_opnd(Wk, 128, smem, SM_WH, SM_WL, tid);
    __syncthreads();
    mma_compute(sbase, wid, lane, c);
    epilogue_store(c, bk, nullptr, outk, row0, rows, 0, wid, lane);
    __syncthreads();

    stage_opnd(Wv, 128, smem, SM_WH, SM_WL, tid);
    __syncthreads();
    mma_compute(sbase, wid, lane, c);
    epilogue_store(c, bv, nullptr, outv, row0, rows, 0, wid, lane);
}

// ======================= attention + pool (fp32) ============================
// 1-exp online softmax: rescale only when the running max increases.

__global__ void k_attn(const float* __restrict__ q,
                       const float* __restrict__ k,
                       const float* __restrict__ v,
                       float* __restrict__ ctx,
                       const int* __restrict__ lengths) {
    __shared__ float Ks[MAXLEN * 32];
    __shared__ float Vs[MAXLEN * 32];
    int s = blockIdx.x, h = blockIdx.y;
    int L = lengths[s];
    int n0 = g_starts[s];
    int tid = threadIdx.x;

    for (int i = tid; i < L * 32; i += MAXLEN) {
        int j = i >> 5, d = i & 31;
        size_t base = (size_t)(n0 + j) * 128 + h * 32 + d;
        Ks[i] = k[base];
        Vs[i] = v[base];
    }
    __syncthreads();
    if (tid >= L) return;

    float4 qv[8];
    const float4* q4 = (const float4*)(q + (size_t)(n0 + tid) * 128 + h * 32);
    #pragma unroll
    for (int d4 = 0; d4 < 8; d4++) {
        float4 t = q4[d4];
        t.x *= 0.17677669529663687f; t.y *= 0.17677669529663687f;
        t.z *= 0.17677669529663687f; t.w *= 0.17677669529663687f;
        qv[d4] = t;
    }

    float m = -1e30f, l = 0.f;
    float4 acc[8];
    #pragma unroll
    for (int d4 = 0; d4 < 8; d4++) acc[d4] = make_float4(0.f, 0.f, 0.f, 0.f);

    for (int j = 0; j < L; j++) {
        const float4* K4 = (const float4*)(Ks + j * 32);
        float sc = 0.f;
        #pragma unroll
        for (int d4 = 0; d4 < 8; d4++) {
            float4 kk = K4[d4];
            sc += qv[d4].x * kk.x + qv[d4].y * kk.y + qv[d4].z * kk.z + qv[d4].w * kk.w;
        }
        float e;
        if (sc <= m) {
            e = __expf(sc - m);
        } else {
            float r = __expf(m - sc);   // 0 on first iteration (m=-1e30)
            l *= r;
            #pragma unroll
            for (int d4 = 0; d4 < 8; d4++) {
                acc[d4].x *= r; acc[d4].y *= r; acc[d4].z *= r; acc[d4].w *= r;
            }
            m = sc;
            e = 1.f;
        }
        l += e;
        const float4* V4 = (const float4*)(Vs + j * 32);
        #pragma unroll
        for (int d4 = 0; d4 < 8; d4++) {
            float4 vv = V4[d4];
            acc[d4].x += e * vv.x;
            acc[d4].y += e * vv.y;
            acc[d4].z += e * vv.z;
            acc[d4].w += e * vv.w;
        }
    }
    float invl = 1.f / l;
    float4* o = (float4*)(ctx + (size_t)(n0 + tid) * 128 + h * 32);
    #pragma unroll
    for (int d4 = 0; d4 < 8; d4++) {
        float4 a = acc[d4];
        o[d4] = make_float4(a.x * invl, a.y * invl, a.z * invl, a.w * invl);
    }
}

__global__ void k_pool(const float* __restrict__ a,
                       const int* __restrict__ lengths,
                       float* __restrict__ out) {
    int s = blockIdx.x;
    int d = threadIdx.x;
    int L = lengths[s];
    int n0 = g_starts[s];
    float sum = 0.f;
    for (int p = 0; p < L; p++)
        sum += a[(size_t)(n0 + p) * 128 + d];
    out[(size_t)s * 128 + d] = sum / (float)L;
}

// ---------------------------------------------------------------------------
extern "C" void kernel_launch(void* const* d_in, const int* in_sizes, int n_in,
                              void* d_out, int out_size) {
    (void)n_in; (void)out_size;
    const float* POI    = (const float*)d_in[0];
    const float* delta  = (const float*)d_in[1];
    const float* attW   = (const float*)d_in[2];
    const float* a_src  = (const float*)d_in[3];
    const float* a_dst  = (const float*)d_in[4];
    const float* ipw    = (const float*)d_in[5];
    const float* ipb    = (const float*)d_in[6];
    const float* opw    = (const float*)d_in[7];
    const float* opb    = (const float*)d_in[8];
    const float* ln1g   = (const float*)d_in[9];
    const float* ln1b   = (const float*)d_in[10];
    const float* ln2g   = (const float*)d_in[11];
    const float* ln2b   = (const float*)d_in[12];
    const float* f1w    = (const float*)d_in[13];
    const float* f1b    = (const float*)d_in[14];
    const float* f2w    = (const float*)d_in[15];
    const float* f2b    = (const float*)d_in[16];
    const int* sess_idx  = (const int*)d_in[17];
    const int* edge_dist = (const int*)d_in[18];
    const int* batch_ids = (const int*)d_in[20];
    const int* node_pos  = (const int*)d_in[21];
    const int* lengths   = (const int*)d_in[22];

    int N = in_sizes[17];

    float* bufA = nullptr; cudaGetSymbolAddress((void**)&bufA, g_bufA);
    float* bufB = nullptr; cudaGetSymbolAddress((void**)&bufB, g_bufB);
    float* bufC = nullptr; cudaGetSymbolAddress((void**)&bufC, g_bufC);
    float* bufD = nullptr; cudaGetSymbolAddress((void**)&bufD, g_bufD);
    float* bufE = nullptr; cudaGetSymbolAddress((void**)&bufE, g_bufE);
    float* bufF = nullptr; cudaGetSymbolAddress((void**)&bufF, g_bufF);
    float* bufG = nullptr; cudaGetSymbolAddress((void**)&bufG, g_bufG);

    float* bH    = bufB;   // GAT output
    float* bQ    = bufC;   // LN1 output (attn residual)
    float* bq    = bufD;   // q projection
    float* bk    = bufE;   // k projection
    float* bv    = bufF;   // v projection
    float* bctx  = bufA;   // attention context
    float* bo    = bufB;   // out_proj result     (bH dead after gemm_kv)
    float* bout2 = bufG;   // LN2 output
    float* bf1   = bufC;   // ffn hidden          (bQ dead after k_ln)
    float* bf2   = bufD;   // ffn out + residual  (bq dead after attn)

    cudaFuncSetAttribute(gemm_mma, cudaFuncAttributeMaxDynamicSharedMemorySize, SM_TOTAL);
    cudaFuncSetAttribute(gemm_kv,  cudaFuncAttributeMaxDynamicSharedMemorySize, SM_TOTAL);

    int wgrid = (N * 32 + 255) / 256;
    int gb = (N + 127) / 128;

    k_prep<<<2, BSESS>>>(attW, a_src, a_dst, lengths);
    k_hg<<<wgrid, 256>>>(POI, delta, sess_idx, edge_dist, batch_ids, node_pos,
                         lengths, ln1g, ln1b, bH, bQ, N);

    gemm_mma<<<gb, 256, SM_TOTAL>>>(bQ, ipw, ipb, nullptr, bq, N, 0);
    gemm_kv<<<gb, 256, SM_TOTAL>>>(bH, ipw + 128 * 128, ipb + 128,
                                   ipw + 256 * 128, ipb + 256, bk, bv, N);

    k_attn<<<dim3(BSESS, 4), MAXLEN>>>(bq, bk, bv, bctx, lengths);

    gemm_mma<<<gb, 256, SM_TOTAL>>>(bctx, opw, opb, nullptr, bo, N, 0);
    k_ln<<<wgrid, 256>>>(bo, bQ, ln2g, ln2b, bout2, N);

    gemm_mma<<<gb, 256, SM_TOTAL>>>(bout2, f1w, f1b, nullptr, bf1, N, 1);
    gemm_mma<<<gb, 256, SM_TOTAL>>>(bf1,   f2w, f2b, bout2,  bf2, N, 0);

    k_pool<<<BSESS, 128>>>(bf2, lengths, (float*)d_out);
}